// round 1
// baseline (speedup 1.0000x reference)
#include <cuda_runtime.h>

// FullConvolution rulebook sparse conv:
//   out[rules_out[k,r], :] += features[rules_in[k,r], :] @ weight[k, :, :]
//   out += bias (everywhere)
// C_in = C_out = 64 (specialized).
//
// Strategy (round 0): exact-fp32, FMA-pipe-bound GEMM using packed fma.rn.f32x2
// (sm_100+), smem-staged weight + transposed gathered features, vectorized
// red.global.add.v4.f32 scatter.

#define C_DIM 64
#define TILE_R 128
#define NTHREADS 128

// smem: W (64*64 f32) + featT (64*128 f32, [c][r]) + outIdx (128 i32)
#define SMEM_FLOATS (C_DIM * C_DIM + C_DIM * TILE_R)
#define SMEM_BYTES  (SMEM_FLOATS * 4 + TILE_R * 4)

__device__ __forceinline__ unsigned long long dup2(float a) {
    unsigned long long r;
    asm("mov.b64 %0, {%1, %1};" : "=l"(r) : "f"(a));
    return r;
}

__device__ __forceinline__ void ffma2(unsigned long long &d,
                                      unsigned long long a,
                                      unsigned long long b) {
    asm("fma.rn.f32x2 %0, %1, %2, %0;" : "+l"(d) : "l"(a), "l"(b));
}

__device__ __forceinline__ void red_add_v4(float* addr, float x, float y, float z, float w) {
    asm volatile("red.global.add.v4.f32 [%0], {%1, %2, %3, %4};"
                 :: "l"(addr), "f"(x), "f"(y), "f"(z), "f"(w) : "memory");
}

__global__ void __launch_bounds__(NTHREADS)
conv_rulebook_kernel(const float* __restrict__ features,
                     const float* __restrict__ weight,
                     const int* __restrict__ rules_in,
                     const int* __restrict__ rules_out,
                     float* __restrict__ out,
                     int n_rows)
{
    extern __shared__ float smem[];
    float* w_s   = smem;                      // [64][64]
    float* featT = smem + C_DIM * C_DIM;      // [64][128]  ([c][r])
    int*   oidx  = (int*)(smem + SMEM_FLOATS);

    const int tid  = threadIdx.x;
    const int k    = blockIdx.y;
    const int row0 = blockIdx.x * TILE_R;

    // ---- stage W[k] into smem (16 KB) ----
    {
        const float4* wg  = (const float4*)(weight + (size_t)k * C_DIM * C_DIM);
        float4*       ws4 = (float4*)w_s;
        #pragma unroll
        for (int i = tid; i < C_DIM * C_DIM / 4; i += NTHREADS)
            ws4[i] = wg[i];
    }

    // ---- gather: one rule per thread, store transposed into smem ----
    {
        const int r  = tid;
        const int gr = row0 + r;
        int in_idx = -1, out_idx = -1;
        if (gr < n_rows) {
            in_idx  = rules_in[(size_t)k * n_rows + gr];
            out_idx = rules_out[(size_t)k * n_rows + gr];
        }
        oidx[r] = out_idx;
        if (in_idx >= 0) {
            const float4* f = (const float4*)(features + (size_t)in_idx * C_DIM);
            #pragma unroll
            for (int j = 0; j < C_DIM / 4; j++) {
                float4 v = f[j];
                featT[(4 * j + 0) * TILE_R + r] = v.x;
                featT[(4 * j + 1) * TILE_R + r] = v.y;
                featT[(4 * j + 2) * TILE_R + r] = v.z;
                featT[(4 * j + 3) * TILE_R + r] = v.w;
            }
        }
    }
    __syncthreads();

    // ---- register-tiled GEMM: each thread owns 8 rows x 8 output channels ----
    // tr in [0,16): row group; to in [0,8): out-channel group.
    // Within a warp: 4 distinct tr (broadcast-heavy LDS), 8 distinct to.
    const int tr = tid >> 3;
    const int to = tid & 7;

    unsigned long long acc[8][4];
    #pragma unroll
    for (int i = 0; i < 8; i++)
        #pragma unroll
        for (int j = 0; j < 4; j++)
            acc[i][j] = 0ull;

    const float4*     a_base = (const float4*)(featT + tr * 8);      // stride 32 float4 per c
    const ulonglong2* w_base = (const ulonglong2*)(w_s + to * 8);    // stride 16 ull2 per c

    #pragma unroll 8
    for (int c = 0; c < C_DIM; c++) {
        float4 a0 = a_base[c * (TILE_R / 4) + 0];
        float4 a1 = a_base[c * (TILE_R / 4) + 1];
        ulonglong2 w01 = w_base[c * (C_DIM / 2 / 4) * 2];       // = w_base[c*16]
        ulonglong2 w23 = w_base[c * (C_DIM / 2 / 4) * 2 + 1];   // = w_base[c*16+1]

        unsigned long long ad[8];
        ad[0] = dup2(a0.x); ad[1] = dup2(a0.y); ad[2] = dup2(a0.z); ad[3] = dup2(a0.w);
        ad[4] = dup2(a1.x); ad[5] = dup2(a1.y); ad[6] = dup2(a1.z); ad[7] = dup2(a1.w);

        #pragma unroll
        for (int i = 0; i < 8; i++) {
            ffma2(acc[i][0], ad[i], w01.x);
            ffma2(acc[i][1], ad[i], w01.y);
            ffma2(acc[i][2], ad[i], w23.x);
            ffma2(acc[i][3], ad[i], w23.y);
        }
    }

    // ---- scatter: vectorized fp32 reductions (2x red.v4 per owned row) ----
    #pragma unroll
    for (int i = 0; i < 8; i++) {
        int oi = oidx[tr * 8 + i];
        if (oi >= 0) {
            float* dst = out + (size_t)oi * C_DIM + to * 8;
            float f0, f1, f2, f3;
            asm("mov.b64 {%0, %1}, %2;" : "=f"(f0), "=f"(f1) : "l"(acc[i][0]));
            asm("mov.b64 {%0, %1}, %2;" : "=f"(f2), "=f"(f3) : "l"(acc[i][1]));
            red_add_v4(dst, f0, f1, f2, f3);
            asm("mov.b64 {%0, %1}, %2;" : "=f"(f0), "=f"(f1) : "l"(acc[i][2]));
            asm("mov.b64 {%0, %1}, %2;" : "=f"(f2), "=f"(f3) : "l"(acc[i][3]));
            red_add_v4(dst + 4, f0, f1, f2, f3);
        }
    }
}

// Initialize every output row to bias (reference adds bias at all output sites;
// d_out is poisoned before timing, so we must write everything).
__global__ void bias_init_kernel(float* __restrict__ out,
                                 const float* __restrict__ bias,
                                 int total4)
{
    int i = blockIdx.x * blockDim.x + threadIdx.x;
    if (i < total4) {
        const float4* b4 = (const float4*)bias;
        ((float4*)out)[i] = b4[i & (C_DIM / 4 - 1)];
    }
}

extern "C" void kernel_launch(void* const* d_in, const int* in_sizes, int n_in,
                              void* d_out, int out_size)
{
    const float* features  = (const float*)d_in[0];
    const float* weight    = (const float*)d_in[1];
    const float* bias      = (const float*)d_in[2];
    const int*   rules_in  = (const int*)d_in[3];
    const int*   rules_out = (const int*)d_in[4];

    const int n_rows = in_sizes[0] / C_DIM;                 // N_IN
    const int K      = in_sizes[3] / n_rows;                // filter volume
    float* out = (float*)d_out;

    // 1) bias broadcast (also initializes the poisoned buffer)
    int total4 = out_size / 4;
    bias_init_kernel<<<(total4 + 255) / 256, 256>>>(out, bias, total4);

    // 2) gather - GEMM - scatter
    cudaFuncSetAttribute(conv_rulebook_kernel,
                         cudaFuncAttributeMaxDynamicSharedMemorySize, SMEM_BYTES);
    dim3 grid((n_rows + TILE_R - 1) / TILE_R, K);
    conv_rulebook_kernel<<<grid, NTHREADS, SMEM_BYTES>>>(
        features, weight, rules_in, rules_out, out, n_rows);
}

// round 3
// speedup vs baseline: 1.5828x; 1.5828x over previous
#include <cuda_runtime.h>
#include <cuda_bf16.h>
#include <cstdint>

// Rulebook sparse conv via legacy tensor-core path (harness targets sm_100,
// NOT sm_100a -> no tcgen05; mma.sync + ldmatrix are baseline PTX).
//   out[rules_out[k,r], :] += features[rules_in[k,r], :] @ weight[k, :, :]
//   out += bias everywhere.  C_in = C_out = 64.
// bf16x3 error-compensated: x = hi + lo (bf16); D = Ah*Bh + Ah*Bl + Al*Bh,
// fp32 accumulate -> residual ~2^-18.

#define C_DIM    64
#define TILE_R   128
#define NTHREADS 128
#define MAXN     100000
#define MAXK     27

// padded smem row stride: 64 bf16 = 128B, pad to 144B (16B aligned; lane-bank
// shift of 4 per row -> conflict-free ldmatrix/STS.128)
#define ROW_B    144

// ---- device-global bf16 hi/lo scratch (allocation-free rule) ----
__device__ __nv_bfloat16 g_feat_hi[MAXN * C_DIM];
__device__ __nv_bfloat16 g_feat_lo[MAXN * C_DIM];
__device__ __nv_bfloat16 g_wt_hi[MAXK * C_DIM * C_DIM];   // [k][cin][cout] (row-major K x N)
__device__ __nv_bfloat16 g_wt_lo[MAXK * C_DIM * C_DIM];

// ---- smem layout (dynamic) ----
#define SMEM_OIDX  0                         // int[128]
#define SMEM_A_HI  512                       // 128 rows x 144B
#define SMEM_A_LO  (SMEM_A_HI + TILE_R * ROW_B)
#define SMEM_W_HI  (SMEM_A_LO + TILE_R * ROW_B)   // 64 rows x 144B ([cin][cout])
#define SMEM_W_LO  (SMEM_W_HI + C_DIM * ROW_B)
#define SMEM_BYTES (SMEM_W_LO + C_DIM * ROW_B)    // 512 + 36864 + 18432 = 55808

__device__ __forceinline__ uint32_t smem_u32(const void* p) {
    uint32_t a;
    asm("{ .reg .u64 t; cvta.to.shared.u64 t, %1; cvt.u32.u64 %0, t; }" : "=r"(a) : "l"(p));
    return a;
}

__device__ __forceinline__ void ldsm4(uint32_t* r, uint32_t addr) {
    asm volatile("ldmatrix.sync.aligned.m8n8.x4.shared.b16 {%0,%1,%2,%3}, [%4];"
                 : "=r"(r[0]), "=r"(r[1]), "=r"(r[2]), "=r"(r[3]) : "r"(addr));
}
__device__ __forceinline__ void ldsm4t(uint32_t* r, uint32_t addr) {
    asm volatile("ldmatrix.sync.aligned.m8n8.x4.trans.shared.b16 {%0,%1,%2,%3}, [%4];"
                 : "=r"(r[0]), "=r"(r[1]), "=r"(r[2]), "=r"(r[3]) : "r"(addr));
}
__device__ __forceinline__ void mma16816(float* c, const uint32_t* a, const uint32_t* b) {
    asm volatile("mma.sync.aligned.m16n8k16.row.col.f32.bf16.bf16.f32 "
                 "{%0,%1,%2,%3}, {%4,%5,%6,%7}, {%8,%9}, {%0,%1,%2,%3};"
                 : "+f"(c[0]), "+f"(c[1]), "+f"(c[2]), "+f"(c[3])
                 : "r"(a[0]), "r"(a[1]), "r"(a[2]), "r"(a[3]), "r"(b[0]), "r"(b[1]));
}
__device__ __forceinline__ void red_add_v2(float* addr, float x, float y) {
    asm volatile("red.global.add.v2.f32 [%0], {%1, %2};"
                 :: "l"(addr), "f"(x), "f"(y) : "memory");
}

// ============================ prep kernels ============================

__global__ void prep_feat_kernel(const float* __restrict__ f, int count4) {
    int i = blockIdx.x * blockDim.x + threadIdx.x;
    if (i >= count4) return;
    float4 v = ((const float4*)f)[i];
    __nv_bfloat16 h0 = __float2bfloat16_rn(v.x), h1 = __float2bfloat16_rn(v.y);
    __nv_bfloat16 h2 = __float2bfloat16_rn(v.z), h3 = __float2bfloat16_rn(v.w);
    __nv_bfloat16 l0 = __float2bfloat16_rn(v.x - __bfloat162float(h0));
    __nv_bfloat16 l1 = __float2bfloat16_rn(v.y - __bfloat162float(h1));
    __nv_bfloat16 l2 = __float2bfloat16_rn(v.z - __bfloat162float(h2));
    __nv_bfloat16 l3 = __float2bfloat16_rn(v.w - __bfloat162float(h3));
    ((__nv_bfloat162*)g_feat_hi)[2 * i]     = __nv_bfloat162(h0, h1);
    ((__nv_bfloat162*)g_feat_hi)[2 * i + 1] = __nv_bfloat162(h2, h3);
    ((__nv_bfloat162*)g_feat_lo)[2 * i]     = __nv_bfloat162(l0, l1);
    ((__nv_bfloat162*)g_feat_lo)[2 * i + 1] = __nv_bfloat162(l2, l3);
}

// weight stays [k][cin][cout] (row-major K x N -> B loaded with ldmatrix.trans)
__global__ void prep_wt_kernel(const float* __restrict__ w, int total) {
    int i = blockIdx.x * blockDim.x + threadIdx.x;
    if (i >= total) return;
    float x = w[i];
    __nv_bfloat16 h = __float2bfloat16_rn(x);
    g_wt_hi[i] = h;
    g_wt_lo[i] = __float2bfloat16_rn(x - __bfloat162float(h));
}

__global__ void bias_init_kernel(float* __restrict__ out, const float* __restrict__ bias, int total4) {
    int i = blockIdx.x * blockDim.x + threadIdx.x;
    if (i < total4) {
        const float4* b4 = (const float4*)bias;
        ((float4*)out)[i] = b4[i & (C_DIM / 4 - 1)];
    }
}

// ============================ main kernel ============================

__global__ void __launch_bounds__(NTHREADS, 3)
conv_mma_kernel(const int* __restrict__ rules_in,
                const int* __restrict__ rules_out,
                float* __restrict__ out,
                int n_rows, int tiles_per_k, int total_tiles, int tiles_per_cta)
{
    extern __shared__ char smem[];
    const uint32_t smem_base = smem_u32(smem);
    const int tid = threadIdx.x;
    const int wid = tid >> 5;
    const int lid = tid & 31;
    int* oidx_s = (int*)(smem + SMEM_OIDX);

    int tile0   = blockIdx.x * tiles_per_cta;
    int tileEnd = tile0 + tiles_per_cta;
    if (tileEnd > total_tiles) tileEnd = total_tiles;
    int cur_k = -1;

    for (int tile = tile0; tile < tileEnd; tile++) {
        const int k    = tile / tiles_per_k;
        const int row0 = (tile - k * tiles_per_k) * TILE_R;

        // ---- stage W[k] (hi+lo), rows = cin, 64 bf16 each, padded to 144B ----
        if (k != cur_k) {
            cur_k = k;
            const int r = tid & 63;
            const float4* src = (const float4*)(
                ((tid < 64) ? g_wt_hi : g_wt_lo) + ((size_t)k * C_DIM + r) * C_DIM);
            char* dst = smem + ((tid < 64) ? SMEM_W_HI : SMEM_W_LO) + r * ROW_B;
            #pragma unroll
            for (int j = 0; j < 8; j++)
                *(float4*)(dst + j * 16) = src[j];
        }

        // ---- gather one rule/thread into padded smem rows (hi + lo) ----
        {
            const int gr = row0 + tid;
            int in_idx = 0, out_idx = -1;
            if (gr < n_rows) {
                in_idx  = rules_in [(size_t)k * n_rows + gr];
                out_idx = rules_out[(size_t)k * n_rows + gr];
            }
            oidx_s[tid] = out_idx;
            const float4* fh = (const float4*)(g_feat_hi + (size_t)in_idx * C_DIM);
            const float4* fl = (const float4*)(g_feat_lo + (size_t)in_idx * C_DIM);
            char* ah = smem + SMEM_A_HI + tid * ROW_B;
            char* al = smem + SMEM_A_LO + tid * ROW_B;
            #pragma unroll
            for (int j = 0; j < 8; j++) {
                *(float4*)(ah + j * 16) = fh[j];
                *(float4*)(al + j * 16) = fl[j];
            }
        }
        __syncthreads();

        // ---- warp GEMM: 32 rows x 64 cols, K=64, 3 correction terms ----
        float acc[2][8][4];
        #pragma unroll
        for (int mt = 0; mt < 2; mt++)
            #pragma unroll
            for (int nt = 0; nt < 8; nt++)
                #pragma unroll
                for (int e = 0; e < 4; e++) acc[mt][nt][e] = 0.f;

        #pragma unroll
        for (int kc = 0; kc < 4; kc++) {
            // A frags: lanes 0-15 -> rows m0..m0+15 at col k0; lanes 16-31 -> col k0+8
            uint32_t ah[2][4], al[2][4];
            #pragma unroll
            for (int mt = 0; mt < 2; mt++) {
                int arow = wid * 32 + mt * 16 + (lid & 15);
                uint32_t aoff = arow * ROW_B + (kc * 16 + (lid >> 4) * 8) * 2;
                ldsm4(ah[mt], smem_base + SMEM_A_HI + aoff);
                ldsm4(al[mt], smem_base + SMEM_A_LO + aoff);
            }
            // B frags (trans): lanes 0-15 -> k-rows k0..k0+15 at col n0; 16-31 -> n0+8
            uint32_t bh[4][4], bl[4][4];
            #pragma unroll
            for (int nt16 = 0; nt16 < 4; nt16++) {
                int brow = kc * 16 + (lid & 15);
                uint32_t boff = brow * ROW_B + (nt16 * 16 + (lid >> 4) * 8) * 2;
                ldsm4t(bh[nt16], smem_base + SMEM_W_HI + boff);
                ldsm4t(bl[nt16], smem_base + SMEM_W_LO + boff);
            }
            #pragma unroll
            for (int mt = 0; mt < 2; mt++)
                #pragma unroll
                for (int nt16 = 0; nt16 < 4; nt16++) {
                    mma16816(acc[mt][2 * nt16],     ah[mt], &bh[nt16][0]);
                    mma16816(acc[mt][2 * nt16 + 1], ah[mt], &bh[nt16][2]);
                    mma16816(acc[mt][2 * nt16],     ah[mt], &bl[nt16][0]);
                    mma16816(acc[mt][2 * nt16 + 1], ah[mt], &bl[nt16][2]);
                    mma16816(acc[mt][2 * nt16],     al[mt], &bh[nt16][0]);
                    mma16816(acc[mt][2 * nt16 + 1], al[mt], &bh[nt16][2]);
                }
        }

        // ---- scatter: c0,c1 -> row r0, c2,c3 -> row r0+8; cols 8*nt + 2*(l%4) ----
        #pragma unroll
        for (int mt = 0; mt < 2; mt++) {
            const int r0 = wid * 32 + mt * 16 + (lid >> 2);
            const int oiA = oidx_s[r0];
            const int oiB = oidx_s[r0 + 8];
            const int c0  = (lid & 3) * 2;
            if (oiA >= 0) {
                float* dA = out + (size_t)oiA * C_DIM + c0;
                #pragma unroll
                for (int nt = 0; nt < 8; nt++)
                    red_add_v2(dA + nt * 8, acc[mt][nt][0], acc[mt][nt][1]);
            }
            if (oiB >= 0) {
                float* dB = out + (size_t)oiB * C_DIM + c0;
                #pragma unroll
                for (int nt = 0; nt < 8; nt++)
                    red_add_v2(dB + nt * 8, acc[mt][nt][2], acc[mt][nt][3]);
            }
        }
        __syncthreads();   // smem reusable next tile
    }
}

// ============================ launch ============================

extern "C" void kernel_launch(void* const* d_in, const int* in_sizes, int n_in,
                              void* d_out, int out_size)
{
    const float* features  = (const float*)d_in[0];
    const float* weight    = (const float*)d_in[1];
    const float* bias      = (const float*)d_in[2];
    const int*   rules_in  = (const int*)d_in[3];
    const int*   rules_out = (const int*)d_in[4];

    const int n_rows = in_sizes[0] / C_DIM;            // N_IN
    const int K      = in_sizes[1] / (C_DIM * C_DIM);  // filter volume
    float* out = (float*)d_out;

    const int count4 = in_sizes[0] / 4;
    prep_feat_kernel<<<(count4 + 255) / 256, 256>>>(features, count4);
    const int wtot = K * C_DIM * C_DIM;
    prep_wt_kernel<<<(wtot + 255) / 256, 256>>>(weight, wtot);

    const int total4 = out_size / 4;
    bias_init_kernel<<<(total4 + 255) / 256, 256>>>(out, bias, total4);

    const int tiles_per_k   = (n_rows + TILE_R - 1) / TILE_R;
    const int total_tiles   = K * tiles_per_k;
    const int NCTA          = 444;  // 148 SMs x 3
    const int tiles_per_cta = (total_tiles + NCTA - 1) / NCTA;

    cudaFuncSetAttribute(conv_mma_kernel,
                         cudaFuncAttributeMaxDynamicSharedMemorySize, SMEM_BYTES);
    conv_mma_kernel<<<NCTA, NTHREADS, SMEM_BYTES>>>(
        rules_in, rules_out, out, n_rows, tiles_per_k, total_tiles, tiles_per_cta);
}